// round 1
// baseline (speedup 1.0000x reference)
#include <cuda_runtime.h>
#include <math.h>

// Problem constants
#define Bq   2
#define Sq   2048
#define Eq   1024
#define Hq   16
#define Dq   64
#define QKVq 1152    // (16 + 2*1) * 64
#define KOFF 1024    // k offset within qkv row
#define VOFF 1088    // v offset within qkv row

// Scratch (device globals — no runtime allocation allowed)
__device__ float g_qkv[Bq * Sq * QKVq];          // QKV projection output
__device__ float g_attn[Bq * Sq * Eq];           // attention output [b, s, h*64+d]
__device__ float g_cos[Sq * (Dq / 2)];
__device__ float g_sin[Sq * (Dq / 2)];

// ---------------------------------------------------------------------------
// RoPE tables: cos/sin(pos * theta^(-2i/64)), computed in double for accuracy
// ---------------------------------------------------------------------------
__global__ void rope_tables_kernel() {
    int idx = blockIdx.x * blockDim.x + threadIdx.x;
    if (idx >= Sq * (Dq / 2)) return;
    int s = idx >> 5;
    int i = idx & 31;
    double inv = exp(-(2.0 * i / 64.0) * log(10000.0));
    double ang = (double)s * inv;
    g_cos[idx] = (float)cos(ang);
    g_sin[idx] = (float)sin(ang);
}

// ---------------------------------------------------------------------------
// GEMM (NT): C[m][n] = sum_k A[m][k] * W[n][k] + bias[n]
// M = 4096, K = 1024 fixed; N template. Block tile 64x64, BK=16, 256 threads,
// 4x4 micro-tile per thread, float4 shared loads.
// ---------------------------------------------------------------------------
template <int N>
__device__ __forceinline__ void gemm_body(const float* __restrict__ A,
                                          const float* __restrict__ W,
                                          const float* __restrict__ bias,
                                          float* __restrict__ C) {
    constexpr int K = 1024;
    __shared__ float As[16][68];
    __shared__ float Bs[16][68];

    const int tid  = threadIdx.x;
    const int bm   = blockIdx.y * 64;
    const int bn   = blockIdx.x * 64;
    const int tm   = (tid >> 4) * 4;   // 0..60
    const int tn   = (tid & 15) * 4;   // 0..60
    const int lrow = tid >> 2;         // 0..63
    const int lk   = (tid & 3) * 4;    // 0,4,8,12

    const float* Ap = A + (size_t)(bm + lrow) * K + lk;
    const float* Wp = W + (size_t)(bn + lrow) * K + lk;

    float acc[4][4];
#pragma unroll
    for (int i = 0; i < 4; i++)
#pragma unroll
        for (int j = 0; j < 4; j++) acc[i][j] = 0.f;

    for (int k0 = 0; k0 < K; k0 += 16) {
        float4 a4 = *(const float4*)(Ap + k0);
        float4 b4 = *(const float4*)(Wp + k0);
        As[lk + 0][lrow] = a4.x; As[lk + 1][lrow] = a4.y;
        As[lk + 2][lrow] = a4.z; As[lk + 3][lrow] = a4.w;
        Bs[lk + 0][lrow] = b4.x; Bs[lk + 1][lrow] = b4.y;
        Bs[lk + 2][lrow] = b4.z; Bs[lk + 3][lrow] = b4.w;
        __syncthreads();
#pragma unroll
        for (int kk = 0; kk < 16; kk++) {
            float4 av = *(const float4*)&As[kk][tm];
            float4 bv = *(const float4*)&Bs[kk][tn];
            float a[4] = {av.x, av.y, av.z, av.w};
            float b[4] = {bv.x, bv.y, bv.z, bv.w};
#pragma unroll
            for (int i = 0; i < 4; i++)
#pragma unroll
                for (int j = 0; j < 4; j++)
                    acc[i][j] = fmaf(a[i], b[j], acc[i][j]);
        }
        __syncthreads();
    }

    float4 b4 = *(const float4*)&bias[bn + tn];
#pragma unroll
    for (int i = 0; i < 4; i++) {
        float4 o;
        o.x = acc[i][0] + b4.x;
        o.y = acc[i][1] + b4.y;
        o.z = acc[i][2] + b4.z;
        o.w = acc[i][3] + b4.w;
        *(float4*)&C[(size_t)(bm + tm + i) * N + bn + tn] = o;
    }
}

__global__ __launch_bounds__(256) void gemm_qkv_kernel(const float* __restrict__ x,
                                                       const float* __restrict__ w,
                                                       const float* __restrict__ bias) {
    gemm_body<QKVq>(x, w, bias, g_qkv);
}

__global__ __launch_bounds__(256) void gemm_out_kernel(const float* __restrict__ w,
                                                       const float* __restrict__ bias,
                                                       float* __restrict__ out) {
    gemm_body<Eq>(g_attn, w, bias, out);
}

// ---------------------------------------------------------------------------
// RoPE apply: interleaved pairs (2i, 2i+1) on q (16 heads) and k (1 head)
// ---------------------------------------------------------------------------
__global__ void rope_apply_kernel() {
    const int total = Bq * Sq * 17 * 32;
    int idx = blockIdx.x * blockDim.x + threadIdx.x;
    if (idx >= total) return;
    int i    = idx & 31;
    int rest = idx >> 5;
    int hh   = rest % 17;
    int bs   = rest / 17;        // b*S + s
    int s    = bs & (Sq - 1);

    float c  = g_cos[s * 32 + i];
    float sn = g_sin[s * 32 + i];
    int col  = (hh < 16) ? (hh * 64 + 2 * i) : (KOFF + 2 * i);

    float* p = g_qkv + (size_t)bs * QKVq + col;
    float2 v = *(float2*)p;
    float2 o;
    o.x = v.x * c - v.y * sn;
    o.y = v.x * sn + v.y * c;
    *(float2*)p = o;
}

// ---------------------------------------------------------------------------
// Flash-style causal MQA attention.
// Grid: (S/16, H, B), 128 threads (4 warps). Each warp owns 4 query rows.
// Key/Value streamed through shared in 64-row tiles (only up to the diagonal).
// Softmax scale folded into Q at load.
// ---------------------------------------------------------------------------
__global__ __launch_bounds__(128) void attn_kernel() {
    const int b     = blockIdx.z;
    const int h     = blockIdx.y;
    const int qbase = blockIdx.x * 16;
    const int tid   = threadIdx.x;
    const int w     = tid >> 5;
    const int lane  = tid & 31;

    __shared__ float Qs[16][64];
    __shared__ float KsT[64][65];    // KsT[d][j]
    __shared__ float Vs[64][64];     // Vs[j][d]
    __shared__ float Ps[4][4][64];   // [warp][row][key]

    const float* base = g_qkv + (size_t)b * Sq * QKVq;

    // Load Q (scaled by 1/sqrt(D) = 0.125)
    for (int u = tid; u < 256; u += 128) {
        int row = u >> 4;
        int g   = (u & 15) * 4;
        float4 v = *(const float4*)(base + (size_t)(qbase + row) * QKVq + h * 64 + g);
        float4 sv = make_float4(v.x * 0.125f, v.y * 0.125f, v.z * 0.125f, v.w * 0.125f);
        *(float4*)&Qs[row][g] = sv;
    }

    float o[4][2];
    float mr[4], lr[4];
#pragma unroll
    for (int r = 0; r < 4; r++) {
        o[r][0] = 0.f; o[r][1] = 0.f;
        mr[r] = -1e30f; lr[r] = 0.f;
    }

    const int tEnd = (qbase + 15) >> 6;
    for (int t = 0; t <= tEnd; t++) {
        const int kb = t * 64;
        __syncthreads();   // protect KsT/Vs reuse (+ Qs visibility on t==0)

        // Load K (transposed) and V tiles
        for (int u = tid; u < 1024; u += 128) {
            int j = u >> 4;
            int g = (u & 15) * 4;
            const float* krow = base + (size_t)(kb + j) * QKVq;
            float4 kv = *(const float4*)(krow + KOFF + g);
            KsT[g + 0][j] = kv.x; KsT[g + 1][j] = kv.y;
            KsT[g + 2][j] = kv.z; KsT[g + 3][j] = kv.w;
            float4 vv = *(const float4*)(krow + VOFF + g);
            *(float4*)&Vs[j][g] = vv;
        }
        __syncthreads();

        // Scores: s[r][half] = q_r . k_{lane(+32)}
        float s[4][2];
#pragma unroll
        for (int r = 0; r < 4; r++) { s[r][0] = 0.f; s[r][1] = 0.f; }
#pragma unroll
        for (int d4 = 0; d4 < 64; d4 += 4) {
            float k0[4], k1[4];
#pragma unroll
            for (int i = 0; i < 4; i++) {
                k0[i] = KsT[d4 + i][lane];
                k1[i] = KsT[d4 + i][lane + 32];
            }
#pragma unroll
            for (int r = 0; r < 4; r++) {
                float4 q = *(const float4*)&Qs[w * 4 + r][d4];
                s[r][0] = fmaf(q.x, k0[0], fmaf(q.y, k0[1], fmaf(q.z, k0[2], fmaf(q.w, k0[3], s[r][0]))));
                s[r][1] = fmaf(q.x, k1[0], fmaf(q.y, k1[1], fmaf(q.z, k1[2], fmaf(q.w, k1[3], s[r][1]))));
            }
        }

        // Online softmax per row
#pragma unroll
        for (int r = 0; r < 4; r++) {
            int qpos = qbase + w * 4 + r;
            float v0 = (kb + lane      <= qpos) ? s[r][0] : -1e30f;
            float v1 = (kb + lane + 32 <= qpos) ? s[r][1] : -1e30f;
            float tmax = fmaxf(v0, v1);
#pragma unroll
            for (int off = 16; off > 0; off >>= 1)
                tmax = fmaxf(tmax, __shfl_xor_sync(0xFFFFFFFFu, tmax, off));
            float mnew = fmaxf(mr[r], tmax);
            float p0 = __expf(v0 - mnew);
            float p1 = __expf(v1 - mnew);
            float ps = p0 + p1;
#pragma unroll
            for (int off = 16; off > 0; off >>= 1)
                ps += __shfl_xor_sync(0xFFFFFFFFu, ps, off);
            float corr = __expf(mr[r] - mnew);
            lr[r] = lr[r] * corr + ps;
            mr[r] = mnew;
            o[r][0] *= corr;
            o[r][1] *= corr;
            Ps[w][r][lane]      = p0;
            Ps[w][r][lane + 32] = p1;
        }
        __syncwarp();

        // PV accumulation: o[r][d] += sum_j p[r][j] * V[j][d]
#pragma unroll 8
        for (int j = 0; j < 64; j++) {
            float v0 = Vs[j][lane];
            float v1 = Vs[j][lane + 32];
#pragma unroll
            for (int r = 0; r < 4; r++) {
                float p = Ps[w][r][j];
                o[r][0] = fmaf(p, v0, o[r][0]);
                o[r][1] = fmaf(p, v1, o[r][1]);
            }
        }
    }

    // Write output: g_attn[b][qpos][h*64 + d]
#pragma unroll
    for (int r = 0; r < 4; r++) {
        int qpos = qbase + w * 4 + r;
        float inv = 1.f / lr[r];
        float* dst = g_attn + ((size_t)(b * Sq + qpos)) * Eq + h * 64;
        dst[lane]      = o[r][0] * inv;
        dst[lane + 32] = o[r][1] * inv;
    }
}

// ---------------------------------------------------------------------------
extern "C" void kernel_launch(void* const* d_in, const int* in_sizes, int n_in,
                              void* d_out, int out_size) {
    const float* x     = (const float*)d_in[0];
    const float* qkv_w = (const float*)d_in[1];
    const float* qkv_b = (const float*)d_in[2];
    const float* out_w = (const float*)d_in[3];
    const float* out_b = (const float*)d_in[4];
    float* out = (float*)d_out;

    // 1. RoPE tables
    rope_tables_kernel<<<(Sq * 32 + 255) / 256, 256>>>();

    // 2. QKV projection: [4096,1024] x [1152,1024]^T + bias -> g_qkv
    gemm_qkv_kernel<<<dim3(QKVq / 64, (Bq * Sq) / 64), 256>>>(x, qkv_w, qkv_b);

    // 3. RoPE on q and k (in place)
    {
        int total = Bq * Sq * 17 * 32;
        rope_apply_kernel<<<(total + 255) / 256, 256>>>();
    }

    // 4. Causal MQA attention -> g_attn
    attn_kernel<<<dim3(Sq / 16, Hq, Bq), 128>>>();

    // 5. Output projection: [4096,1024] x [1024,1024]^T + bias -> out
    gemm_out_kernel<<<dim3(Eq / 64, (Bq * Sq) / 64), 256>>>(out_w, out_b, out);
}

// round 2
// speedup vs baseline: 2.9937x; 2.9937x over previous
#include <cuda_runtime.h>
#include <math.h>

// Problem constants
#define Bq   2
#define Sq   2048
#define Eq   1024
#define Hq   16
#define Dq   64
#define QKVq 1152    // (16 + 2*1) * 64
#define KOFF 1024
#define VOFF 1088

// Scratch (device globals — no runtime allocation allowed)
__device__ float g_qkv[Bq * Sq * QKVq];
__device__ float g_attn[Bq * Sq * Eq];
__device__ float g_cos[Sq * (Dq / 2)];
__device__ float g_sin[Sq * (Dq / 2)];

// ---------------------------------------------------------------------------
// Helpers: tf32 convert + m16n8k8 tf32 MMA
// ---------------------------------------------------------------------------
__device__ __forceinline__ unsigned f2tf32(float x) {
    unsigned r;
    asm("cvt.rna.tf32.f32 %0, %1;" : "=r"(r) : "f"(x));
    return r;
}

__device__ __forceinline__ void mma_tf32(float* d, const unsigned* a,
                                         unsigned b0, unsigned b1) {
    asm volatile(
        "mma.sync.aligned.m16n8k8.row.col.f32.tf32.tf32.f32 "
        "{%0,%1,%2,%3}, {%4,%5,%6,%7}, {%8,%9}, {%0,%1,%2,%3};\n"
        : "+f"(d[0]), "+f"(d[1]), "+f"(d[2]), "+f"(d[3])
        : "r"(a[0]), "r"(a[1]), "r"(a[2]), "r"(a[3]), "r"(b0), "r"(b1));
}

// ---------------------------------------------------------------------------
// RoPE tables
// ---------------------------------------------------------------------------
__global__ void rope_tables_kernel() {
    int idx = blockIdx.x * blockDim.x + threadIdx.x;
    if (idx >= Sq * (Dq / 2)) return;
    int s = idx >> 5;
    int i = idx & 31;
    double inv = exp(-(2.0 * i / 64.0) * log(10000.0));
    double ang = (double)s * inv;
    g_cos[idx] = (float)cos(ang);
    g_sin[idx] = (float)sin(ang);
}

// ---------------------------------------------------------------------------
// RoPE apply (in place on g_qkv): pairs (2i, 2i+1), q heads + 1 k head
// ---------------------------------------------------------------------------
__global__ void rope_apply_kernel() {
    const int total = Bq * Sq * 17 * 32;
    int idx = blockIdx.x * blockDim.x + threadIdx.x;
    if (idx >= total) return;
    int i    = idx & 31;
    int rest = idx >> 5;
    int hh   = rest % 17;
    int bs   = rest / 17;
    int s    = bs & (Sq - 1);

    float c  = g_cos[s * 32 + i];
    float sn = g_sin[s * 32 + i];
    int col  = (hh < 16) ? (hh * 64 + 2 * i) : (KOFF + 2 * i);

    float* p = g_qkv + (size_t)bs * QKVq + col;
    float2 v = *(float2*)p;
    float2 o;
    o.x = v.x * c - v.y * sn;
    o.y = v.x * sn + v.y * c;
    *(float2*)p = o;
}

// ---------------------------------------------------------------------------
// Tensor-core GEMM (NT): C[m][n] = sum_k A[m][k]*W[n][k] + bias[n]
// tf32 mma.m16n8k8. Block 128x64, BK=32, 256 thr (8 warps: 4m x 2n),
// warp tile 32x32 (2 mtiles x 4 ntiles).
// Shared stride 36 words -> fragment loads bank-conflict-free (4g+t).
// ---------------------------------------------------------------------------
template <int N>
__device__ __forceinline__ void gemm_tc_body(const float* __restrict__ A,
                                             const float* __restrict__ W,
                                             const float* __restrict__ bias,
                                             float* __restrict__ C) {
    __shared__ unsigned As[128][36];
    __shared__ unsigned Bs[64][36];

    const int tid  = threadIdx.x;
    const int warp = tid >> 5;
    const int lane = tid & 31;
    const int g    = lane >> 2;
    const int tq   = lane & 3;
    const int wm   = (warp & 3) * 32;
    const int wn   = (warp >> 2) * 32;
    const int bm   = blockIdx.y * 128;
    const int bn   = blockIdx.x * 64;

    const int srow = tid >> 3;        // 0..31
    const int skc  = (tid & 7) * 4;   // 0..28

    float acc[2][4][4];
#pragma unroll
    for (int mt = 0; mt < 2; mt++)
#pragma unroll
        for (int nt = 0; nt < 4; nt++)
#pragma unroll
            for (int i = 0; i < 4; i++) acc[mt][nt][i] = 0.f;

    for (int k0 = 0; k0 < 1024; k0 += 32) {
        // Stage A (128x32) and B (64x32), converting to tf32
#pragma unroll
        for (int it = 0; it < 4; it++) {
            int m = srow + it * 32;
            float4 v = *(const float4*)(A + (size_t)(bm + m) * 1024 + k0 + skc);
            uint4 u;
            u.x = f2tf32(v.x); u.y = f2tf32(v.y);
            u.z = f2tf32(v.z); u.w = f2tf32(v.w);
            *(uint4*)&As[m][skc] = u;
        }
#pragma unroll
        for (int it = 0; it < 2; it++) {
            int n = srow + it * 32;
            float4 v = *(const float4*)(W + (size_t)(bn + n) * 1024 + k0 + skc);
            uint4 u;
            u.x = f2tf32(v.x); u.y = f2tf32(v.y);
            u.z = f2tf32(v.z); u.w = f2tf32(v.w);
            *(uint4*)&Bs[n][skc] = u;
        }
        __syncthreads();

#pragma unroll
        for (int ks = 0; ks < 4; ks++) {
            unsigned a[2][4];
#pragma unroll
            for (int mt = 0; mt < 2; mt++) {
                int r = wm + mt * 16 + g;
                a[mt][0] = As[r][ks * 8 + tq];
                a[mt][1] = As[r + 8][ks * 8 + tq];
                a[mt][2] = As[r][ks * 8 + tq + 4];
                a[mt][3] = As[r + 8][ks * 8 + tq + 4];
            }
#pragma unroll
            for (int nt = 0; nt < 4; nt++) {
                unsigned b0 = Bs[wn + nt * 8 + g][ks * 8 + tq];
                unsigned b1 = Bs[wn + nt * 8 + g][ks * 8 + tq + 4];
                mma_tf32(acc[0][nt], a[0], b0, b1);
                mma_tf32(acc[1][nt], a[1], b0, b1);
            }
        }
        __syncthreads();
    }

    // Epilogue: bias + store
#pragma unroll
    for (int mt = 0; mt < 2; mt++) {
        int m0 = bm + wm + mt * 16 + g;
#pragma unroll
        for (int nt = 0; nt < 4; nt++) {
            int c = bn + wn + nt * 8 + 2 * tq;
            float bv0 = bias[c], bv1 = bias[c + 1];
            float2 o0 = make_float2(acc[mt][nt][0] + bv0, acc[mt][nt][1] + bv1);
            float2 o1 = make_float2(acc[mt][nt][2] + bv0, acc[mt][nt][3] + bv1);
            *(float2*)&C[(size_t)m0 * N + c]       = o0;
            *(float2*)&C[(size_t)(m0 + 8) * N + c] = o1;
        }
    }
}

__global__ __launch_bounds__(256) void gemm_qkv_kernel(const float* __restrict__ x,
                                                       const float* __restrict__ w,
                                                       const float* __restrict__ bias) {
    gemm_tc_body<QKVq>(x, w, bias, g_qkv);
}

__global__ __launch_bounds__(256) void gemm_out_kernel(const float* __restrict__ w,
                                                       const float* __restrict__ bias,
                                                       float* __restrict__ out) {
    gemm_tc_body<Eq>(g_attn, w, bias, out);
}

// ---------------------------------------------------------------------------
// Tensor-core flash attention (causal MQA).
// Block: 64 query rows x 1 head x 1 batch; 128 threads = 4 warps,
// each warp owns 16 query rows. Key tiles of 64.
// smem reuse: QV holds Q (prologue) then V per tile; KP holds K then P.
// ---------------------------------------------------------------------------
__global__ __launch_bounds__(128) void attn_tc_kernel() {
    const int b     = blockIdx.z;
    const int h     = blockIdx.y;
    const int qb    = blockIdx.x;
    const int qbase = qb * 64;
    const int tid   = threadIdx.x;
    const int w     = tid >> 5;
    const int lane  = tid & 31;
    const int g     = lane >> 2;
    const int tq    = lane & 3;

    __shared__ unsigned QV[64][72];   // Q, then V   (stride 72: 8g+t free for V b-frags)
    __shared__ unsigned KP[64][68];   // K, then P   (stride 68: 4g+t free for frags)

    const float* base = g_qkv + (size_t)b * Sq * QKVq;

    const int srow = tid >> 4;        // 0..7
    const int sc4  = (tid & 15) * 4;  // 0..60

    // Stage Q (scaled by 1/8, tf32)
#pragma unroll
    for (int it = 0; it < 8; it++) {
        int r = srow + it * 8;
        float4 v = *(const float4*)(base + (size_t)(qbase + r) * QKVq + h * 64 + sc4);
        uint4 u;
        u.x = f2tf32(v.x * 0.125f); u.y = f2tf32(v.y * 0.125f);
        u.z = f2tf32(v.z * 0.125f); u.w = f2tf32(v.w * 0.125f);
        *(uint4*)&QV[r][sc4] = u;
    }
    __syncthreads();

    // Preload Q fragments (row block w*16): 8 k-steps x 4 regs
    const int r0 = w * 16 + g;
    unsigned qa[8][4];
#pragma unroll
    for (int ks = 0; ks < 8; ks++) {
        qa[ks][0] = QV[r0][ks * 8 + tq];
        qa[ks][1] = QV[r0 + 8][ks * 8 + tq];
        qa[ks][2] = QV[r0][ks * 8 + tq + 4];
        qa[ks][3] = QV[r0 + 8][ks * 8 + tq + 4];
    }

    float o[8][4];
#pragma unroll
    for (int nt = 0; nt < 8; nt++)
#pragma unroll
        for (int i = 0; i < 4; i++) o[nt][i] = 0.f;
    float mr0 = -1e30f, mr1 = -1e30f, l0 = 0.f, l1 = 0.f;
    const int qpos0 = qbase + w * 16 + g;
    const int qpos1 = qpos0 + 8;

    for (int kt = 0; kt <= qb; kt++) {
        const int kb = kt * 64;
        __syncthreads();   // QV (Q-frags/prev V) and KP (prev P) free

        // Stage K -> KP, V -> QV (tf32)
#pragma unroll
        for (int it = 0; it < 8; it++) {
            int r = srow + it * 8;
            const float* src = base + (size_t)(kb + r) * QKVq;
            float4 kv = *(const float4*)(src + KOFF + sc4);
            float4 vv = *(const float4*)(src + VOFF + sc4);
            uint4 uk, uv;
            uk.x = f2tf32(kv.x); uk.y = f2tf32(kv.y);
            uk.z = f2tf32(kv.z); uk.w = f2tf32(kv.w);
            uv.x = f2tf32(vv.x); uv.y = f2tf32(vv.y);
            uv.z = f2tf32(vv.z); uv.w = f2tf32(vv.w);
            *(uint4*)&KP[r][sc4] = uk;
            *(uint4*)&QV[r][sc4] = uv;
        }
        __syncthreads();

        // S = Q K^T (16 x 64 per warp)
        float sc[8][4];
#pragma unroll
        for (int nt = 0; nt < 8; nt++)
#pragma unroll
            for (int i = 0; i < 4; i++) sc[nt][i] = 0.f;
#pragma unroll
        for (int ks = 0; ks < 8; ks++) {
#pragma unroll
            for (int nt = 0; nt < 8; nt++) {
                unsigned b0 = KP[nt * 8 + g][ks * 8 + tq];
                unsigned b1 = KP[nt * 8 + g][ks * 8 + tq + 4];
                mma_tf32(sc[nt], qa[ks], b0, b1);
            }
        }

        // Causal mask (diagonal tile only)
        if (kt == qb) {
#pragma unroll
            for (int nt = 0; nt < 8; nt++) {
                int key = kb + nt * 8 + 2 * tq;
                if (key > qpos0)     sc[nt][0] = -1e30f;
                if (key + 1 > qpos0) sc[nt][1] = -1e30f;
                if (key > qpos1)     sc[nt][2] = -1e30f;
                if (key + 1 > qpos1) sc[nt][3] = -1e30f;
            }
        }

        // Online softmax (rows g and g+8; quad = lanes sharing g)
        float mx0 = -1e30f, mx1 = -1e30f;
#pragma unroll
        for (int nt = 0; nt < 8; nt++) {
            mx0 = fmaxf(mx0, fmaxf(sc[nt][0], sc[nt][1]));
            mx1 = fmaxf(mx1, fmaxf(sc[nt][2], sc[nt][3]));
        }
        mx0 = fmaxf(mx0, __shfl_xor_sync(0xFFFFFFFFu, mx0, 1));
        mx0 = fmaxf(mx0, __shfl_xor_sync(0xFFFFFFFFu, mx0, 2));
        mx1 = fmaxf(mx1, __shfl_xor_sync(0xFFFFFFFFu, mx1, 1));
        mx1 = fmaxf(mx1, __shfl_xor_sync(0xFFFFFFFFu, mx1, 2));

        float mn0 = fmaxf(mr0, mx0);
        float mn1 = fmaxf(mr1, mx1);
        float corr0 = __expf(mr0 - mn0);
        float corr1 = __expf(mr1 - mn1);
        float sum0 = 0.f, sum1 = 0.f;
#pragma unroll
        for (int nt = 0; nt < 8; nt++) {
            sc[nt][0] = __expf(sc[nt][0] - mn0);
            sc[nt][1] = __expf(sc[nt][1] - mn0);
            sc[nt][2] = __expf(sc[nt][2] - mn1);
            sc[nt][3] = __expf(sc[nt][3] - mn1);
            sum0 += sc[nt][0] + sc[nt][1];
            sum1 += sc[nt][2] + sc[nt][3];
        }
        sum0 += __shfl_xor_sync(0xFFFFFFFFu, sum0, 1);
        sum0 += __shfl_xor_sync(0xFFFFFFFFu, sum0, 2);
        sum1 += __shfl_xor_sync(0xFFFFFFFFu, sum1, 1);
        sum1 += __shfl_xor_sync(0xFFFFFFFFu, sum1, 2);

        mr0 = mn0; mr1 = mn1;
        l0 = l0 * corr0 + sum0;
        l1 = l1 * corr1 + sum1;
#pragma unroll
        for (int nt = 0; nt < 8; nt++) {
            o[nt][0] *= corr0; o[nt][1] *= corr0;
            o[nt][2] *= corr1; o[nt][3] *= corr1;
        }

        __syncthreads();   // all warps finished reading K from KP

        // Store P (tf32) into KP as Ps[row][key] (each warp its own 16 rows)
#pragma unroll
        for (int nt = 0; nt < 8; nt++) {
            uint2 p0, p1;
            p0.x = f2tf32(sc[nt][0]); p0.y = f2tf32(sc[nt][1]);
            p1.x = f2tf32(sc[nt][2]); p1.y = f2tf32(sc[nt][3]);
            *(uint2*)&KP[r0][nt * 8 + 2 * tq]     = p0;
            *(uint2*)&KP[r0 + 8][nt * 8 + 2 * tq] = p1;
        }
        __syncwarp();

        // O += P V
#pragma unroll
        for (int ks = 0; ks < 8; ks++) {
            unsigned pa[4];
            pa[0] = KP[r0][ks * 8 + tq];
            pa[1] = KP[r0 + 8][ks * 8 + tq];
            pa[2] = KP[r0][ks * 8 + tq + 4];
            pa[3] = KP[r0 + 8][ks * 8 + tq + 4];
#pragma unroll
            for (int nt = 0; nt < 8; nt++) {
                unsigned b0 = QV[ks * 8 + tq][nt * 8 + g];
                unsigned b1 = QV[ks * 8 + tq + 4][nt * 8 + g];
                mma_tf32(o[nt], pa, b0, b1);
            }
        }
    }

    // Epilogue: normalize and write g_attn[b][qpos][h*64 + d]
    float inv0 = 1.f / l0;
    float inv1 = 1.f / l1;
    float* dst0 = g_attn + ((size_t)(b * Sq + qpos0)) * Eq + h * 64;
    float* dst1 = g_attn + ((size_t)(b * Sq + qpos1)) * Eq + h * 64;
#pragma unroll
    for (int nt = 0; nt < 8; nt++) {
        int c = nt * 8 + 2 * tq;
        *(float2*)&dst0[c] = make_float2(o[nt][0] * inv0, o[nt][1] * inv0);
        *(float2*)&dst1[c] = make_float2(o[nt][2] * inv1, o[nt][3] * inv1);
    }
}

// ---------------------------------------------------------------------------
extern "C" void kernel_launch(void* const* d_in, const int* in_sizes, int n_in,
                              void* d_out, int out_size) {
    const float* x     = (const float*)d_in[0];
    const float* qkv_w = (const float*)d_in[1];
    const float* qkv_b = (const float*)d_in[2];
    const float* out_w = (const float*)d_in[3];
    const float* out_b = (const float*)d_in[4];
    float* out = (float*)d_out;

    rope_tables_kernel<<<(Sq * 32 + 255) / 256, 256>>>();

    gemm_qkv_kernel<<<dim3(QKVq / 64, (Bq * Sq) / 128), 256>>>(x, qkv_w, qkv_b);

    {
        int total = Bq * Sq * 17 * 32;
        rope_apply_kernel<<<(total + 255) / 256, 256>>>();
    }

    attn_tc_kernel<<<dim3(Sq / 64, Hq, Bq), 128>>>();

    gemm_out_kernel<<<dim3(Eq / 64, (Bq * Sq) / 128), 256>>>(out_w, out_b, out);
}

// round 3
// speedup vs baseline: 4.2720x; 1.4270x over previous
#include <cuda_runtime.h>
#include <math.h>

// Problem constants
#define Bq   2
#define Sq   2048
#define Eq   1024
#define Hq   16
#define QKVq 1152    // (16 + 2*1) * 64
#define KOFF 1024
#define VOFF 1088

// Scratch (device globals — no runtime allocation allowed)
__device__ float    g_qkv[(size_t)Bq * Sq * QKVq];   // QKV GEMM output (fp32)
__device__ unsigned g_q[(size_t)Bq * Sq * Eq];       // tf32, roped, scaled: [b][s][h*64+d]
__device__ unsigned g_k[(size_t)Bq * Sq * 64];       // tf32, roped
__device__ unsigned g_v[(size_t)Bq * Sq * 64];       // tf32
__device__ unsigned g_x32[(size_t)Bq * Sq * Eq];     // x pre-converted to tf32
__device__ unsigned g_w1[(size_t)QKVq * Eq];         // qkv_w tf32
__device__ unsigned g_w2[(size_t)Eq * Eq];           // out_w tf32
__device__ unsigned g_attn[(size_t)Bq * Sq * Eq];    // attention out (tf32)
__device__ float    g_cos[Sq * 32];
__device__ float    g_sin[Sq * 32];

// ---------------------------------------------------------------------------
__device__ __forceinline__ unsigned f2tf32(float x) {
    unsigned r;
    asm("cvt.rna.tf32.f32 %0, %1;" : "=r"(r) : "f"(x));
    return r;
}

__device__ __forceinline__ void mma_tf32(float* d, const unsigned* a,
                                         unsigned b0, unsigned b1) {
    asm volatile(
        "mma.sync.aligned.m16n8k8.row.col.f32.tf32.tf32.f32 "
        "{%0,%1,%2,%3}, {%4,%5,%6,%7}, {%8,%9}, {%0,%1,%2,%3};\n"
        : "+f"(d[0]), "+f"(d[1]), "+f"(d[2]), "+f"(d[3])
        : "r"(a[0]), "r"(a[1]), "r"(a[2]), "r"(a[3]), "r"(b0), "r"(b1));
}

#define CP16(dst, src) asm volatile("cp.async.cg.shared.global [%0], [%1], 16;\n" :: "r"(dst), "l"(src))
#define CPC            asm volatile("cp.async.commit_group;\n")
#define CPW(n)         asm volatile("cp.async.wait_group %0;\n" :: "n"(n))

// ---------------------------------------------------------------------------
// RoPE tables
// ---------------------------------------------------------------------------
__global__ void rope_tables_kernel() {
    int idx = blockIdx.x * blockDim.x + threadIdx.x;
    if (idx >= Sq * 32) return;
    int s = idx >> 5;
    int i = idx & 31;
    double inv = exp(-(2.0 * i / 64.0) * log(10000.0));
    double ang = (double)s * inv;
    g_cos[idx] = (float)cos(ang);
    g_sin[idx] = (float)sin(ang);
}

// ---------------------------------------------------------------------------
// fp32 -> tf32 elementwise converts (weights, x)
// ---------------------------------------------------------------------------
__device__ __forceinline__ void cvt_body(const float4* __restrict__ src,
                                         uint4* __restrict__ dst, int n4) {
    int i = blockIdx.x * blockDim.x + threadIdx.x;
    if (i >= n4) return;
    float4 v = src[i];
    uint4 u;
    u.x = f2tf32(v.x); u.y = f2tf32(v.y);
    u.z = f2tf32(v.z); u.w = f2tf32(v.w);
    dst[i] = u;
}

__global__ void cvt_x_kernel(const float* __restrict__ x) {
    cvt_body((const float4*)x, (uint4*)g_x32, Bq * Sq * Eq / 4);
}
__global__ void cvt_w1_kernel(const float* __restrict__ w) {
    cvt_body((const float4*)w, (uint4*)g_w1, QKVq * Eq / 4);
}
__global__ void cvt_w2_kernel(const float* __restrict__ w) {
    cvt_body((const float4*)w, (uint4*)g_w2, Eq * Eq / 4);
}

// ---------------------------------------------------------------------------
// RoPE + scale + tf32 convert + repack into dense g_q / g_k / g_v
// unit u: 0..15 = q heads (rope, *0.125), 16 = k (rope), 17 = v (copy)
// ---------------------------------------------------------------------------
__global__ void rope_prep_kernel() {
    const int total = Bq * Sq * 18 * 32;
    int idx = blockIdx.x * blockDim.x + threadIdx.x;
    if (idx >= total) return;
    int i    = idx & 31;
    int rest = idx >> 5;
    int u    = rest % 18;
    int bs   = rest / 18;
    int s    = bs & (Sq - 1);

    const float* src = g_qkv + (size_t)bs * QKVq;
    if (u < 16) {
        float c  = g_cos[s * 32 + i];
        float sn = g_sin[s * 32 + i];
        float2 v = *(const float2*)(src + u * 64 + 2 * i);
        uint2 o;
        o.x = f2tf32((v.x * c - v.y * sn) * 0.125f);
        o.y = f2tf32((v.x * sn + v.y * c) * 0.125f);
        *(uint2*)(g_q + (size_t)bs * Eq + u * 64 + 2 * i) = o;
    } else if (u == 16) {
        float c  = g_cos[s * 32 + i];
        float sn = g_sin[s * 32 + i];
        float2 v = *(const float2*)(src + KOFF + 2 * i);
        uint2 o;
        o.x = f2tf32(v.x * c - v.y * sn);
        o.y = f2tf32(v.x * sn + v.y * c);
        *(uint2*)(g_k + (size_t)bs * 64 + 2 * i) = o;
    } else {
        float2 v = *(const float2*)(src + VOFF + 2 * i);
        uint2 o;
        o.x = f2tf32(v.x);
        o.y = f2tf32(v.y);
        *(uint2*)(g_v + (size_t)bs * 64 + 2 * i) = o;
    }
}

// ---------------------------------------------------------------------------
// Double-buffered tf32 tensor GEMM (NT): C = A * W^T + bias
// Block 128x128, BK=32, 256 thr (8 warps: 2m x 4n), warp tile 64x32.
// Inputs already tf32. Dynamic smem: 2*(128*36)*2 matrices = 73728 B.
// ---------------------------------------------------------------------------
template <int N>
__device__ __forceinline__ void gemm_body(const unsigned* __restrict__ A,
                                          const unsigned* __restrict__ W,
                                          const float* __restrict__ bias,
                                          float* __restrict__ C) {
    extern __shared__ unsigned sm[];
    unsigned* sA = sm;                 // [2][128][36]
    unsigned* sB = sm + 2 * 128 * 36;  // [2][128][36]

    const int tid  = threadIdx.x;
    const int warp = tid >> 5;
    const int lane = tid & 31;
    const int g    = lane >> 2;
    const int tq   = lane & 3;
    const int wm   = (warp & 1) * 64;
    const int wn   = (warp >> 1) * 32;
    const int bm   = blockIdx.y * 128;
    const int bn   = blockIdx.x * 128;

    unsigned smb  = (unsigned)__cvta_generic_to_shared(sm);
    unsigned sA_b = smb;
    unsigned sB_b = smb + 2u * 128u * 36u * 4u;

    float acc[4][4][4];
#pragma unroll
    for (int mt = 0; mt < 4; mt++)
#pragma unroll
        for (int nt = 0; nt < 4; nt++)
#pragma unroll
            for (int e = 0; e < 4; e++) acc[mt][nt][e] = 0.f;

    // prologue stage buf 0
#pragma unroll
    for (int i = 0; i < 4; i++) {
        int c = tid + i * 256;
        int r = c >> 3, col = (c & 7) * 4;
        CP16(sA_b + (unsigned)(r * 36 + col) * 4u, A + (size_t)(bm + r) * Eq + col);
        CP16(sB_b + (unsigned)(r * 36 + col) * 4u, W + (size_t)(bn + r) * Eq + col);
    }
    CPC;

    for (int k0 = 0; k0 < Eq; k0 += 32) {
        int buf = (k0 >> 5) & 1;
        if (k0 + 32 < Eq) {
            unsigned da = sA_b + (unsigned)((buf ^ 1) * 4608) * 4u;
            unsigned db = sB_b + (unsigned)((buf ^ 1) * 4608) * 4u;
#pragma unroll
            for (int i = 0; i < 4; i++) {
                int c = tid + i * 256;
                int r = c >> 3, col = (c & 7) * 4;
                CP16(da + (unsigned)(r * 36 + col) * 4u, A + (size_t)(bm + r) * Eq + k0 + 32 + col);
                CP16(db + (unsigned)(r * 36 + col) * 4u, W + (size_t)(bn + r) * Eq + k0 + 32 + col);
            }
            CPC;
            CPW(1);
        } else {
            CPW(0);
        }
        __syncthreads();

        const unsigned* As_ = sA + buf * 4608;
        const unsigned* Bs_ = sB + buf * 4608;
#pragma unroll
        for (int ks = 0; ks < 4; ks++) {
            unsigned a[4][4];
#pragma unroll
            for (int mt = 0; mt < 4; mt++) {
                int r = wm + mt * 16 + g;
                a[mt][0] = As_[r * 36 + ks * 8 + tq];
                a[mt][1] = As_[(r + 8) * 36 + ks * 8 + tq];
                a[mt][2] = As_[r * 36 + ks * 8 + tq + 4];
                a[mt][3] = As_[(r + 8) * 36 + ks * 8 + tq + 4];
            }
#pragma unroll
            for (int nt = 0; nt < 4; nt++) {
                unsigned b0 = Bs_[(wn + nt * 8 + g) * 36 + ks * 8 + tq];
                unsigned b1 = Bs_[(wn + nt * 8 + g) * 36 + ks * 8 + tq + 4];
#pragma unroll
                for (int mt = 0; mt < 4; mt++)
                    mma_tf32(acc[mt][nt], a[mt], b0, b1);
            }
        }
        __syncthreads();
    }

    // Epilogue: bias + store fp32
#pragma unroll
    for (int mt = 0; mt < 4; mt++) {
        int m0 = bm + wm + mt * 16 + g;
#pragma unroll
        for (int nt = 0; nt < 4; nt++) {
            int c = bn + wn + nt * 8 + 2 * tq;
            float bv0 = bias[c], bv1 = bias[c + 1];
            *(float2*)&C[(size_t)m0 * N + c] =
                make_float2(acc[mt][nt][0] + bv0, acc[mt][nt][1] + bv1);
            *(float2*)&C[(size_t)(m0 + 8) * N + c] =
                make_float2(acc[mt][nt][2] + bv0, acc[mt][nt][3] + bv1);
        }
    }
}

__global__ __launch_bounds__(256, 2) void gemm_qkv_kernel(const float* __restrict__ bias) {
    gemm_body<QKVq>(g_x32, g_w1, bias, g_qkv);
}

__global__ __launch_bounds__(256, 2) void gemm_out_kernel(const float* __restrict__ bias,
                                                          float* __restrict__ out) {
    // A = g_attn (tf32). Reinterpret as unsigned GEMM input.
    extern __shared__ unsigned sm[];
    (void)sm;
    gemm_body<Eq>(g_attn, g_w2, bias, out);
}

// ---------------------------------------------------------------------------
// MQA flash attention, tensor-core, cp.async double-buffered.
// Block: 8 seq positions x all 16 heads = 128 mma rows; 256 thr, 8 warps.
// warp w = position qbase + w (16 head-rows). K/V staged ONCE for all heads.
// smem: QP 128x68 (Q then P), Ks 2x64x68, Vs 2x64x72  = 106496 B dynamic.
// ---------------------------------------------------------------------------
__global__ __launch_bounds__(256, 2) void attn_tc_kernel() {
    extern __shared__ unsigned sm[];
    unsigned* QP = sm;                               // 128*68
    unsigned* Ks = sm + 128 * 68;                    // 2*64*68
    unsigned* Vs = sm + 128 * 68 + 2 * 64 * 68;      // 2*64*72

    const int b     = blockIdx.y;
    const int qb    = 255 - (int)blockIdx.x;   // reversed: long blocks first
    const int qbase = qb * 8;
    const int tid   = threadIdx.x;
    const int w     = tid >> 5;
    const int lane  = tid & 31;
    const int g     = lane >> 2;
    const int tq    = lane & 3;

    unsigned smb  = (unsigned)__cvta_generic_to_shared(sm);
    const unsigned qp_b = smb;
    const unsigned ks_b = smb + 128u * 68u * 4u;
    const unsigned vs_b = smb + (128u * 68u + 2u * 64u * 68u) * 4u;

    // Stage Q: row r = pos_local*16 + head
#pragma unroll
    for (int i = 0; i < 8; i++) {
        int c = tid + i * 256;
        int r = c >> 4, col = (c & 15) * 4;
        const unsigned* src = g_q + (((size_t)(b * Sq + qbase + (r >> 4))) << 10)
                              + ((r & 15) << 6) + col;
        CP16(qp_b + (unsigned)(r * 68 + col) * 4u, src);
    }
    CPC;

    const int n_tiles = (qbase + 71) >> 6;

    // Stage KV tile 0
    {
        const unsigned* kp = g_k + ((size_t)(b * Sq)) * 64;
        const unsigned* vp = g_v + ((size_t)(b * Sq)) * 64;
#pragma unroll
        for (int i = 0; i < 4; i++) {
            int c = tid + i * 256;
            int r = c >> 4, col = (c & 15) * 4;
            CP16(ks_b + (unsigned)(r * 68 + col) * 4u, kp + r * 64 + col);
            CP16(vs_b + (unsigned)(r * 72 + col) * 4u, vp + r * 64 + col);
        }
    }
    CPC;
    CPW(1);            // Q done (KV0 may still be in flight)
    __syncthreads();

    // Preload Q fragments (warp's 16 rows), then QP is reused as P buffer
    const int r0 = w * 16 + g;
    unsigned qa[8][4];
#pragma unroll
    for (int ks = 0; ks < 8; ks++) {
        qa[ks][0] = QP[r0 * 68 + ks * 8 + tq];
        qa[ks][1] = QP[(r0 + 8) * 68 + ks * 8 + tq];
        qa[ks][2] = QP[r0 * 68 + ks * 8 + tq + 4];
        qa[ks][3] = QP[(r0 + 8) * 68 + ks * 8 + tq + 4];
    }

    float o[8][4];
#pragma unroll
    for (int nt = 0; nt < 8; nt++)
#pragma unroll
        for (int e = 0; e < 4; e++) o[nt][e] = 0.f;
    float mr0 = -1e30f, mr1 = -1e30f, l0 = 0.f, l1 = 0.f;
    const int qpos = qbase + w;

    for (int kt = 0; kt < n_tiles; kt++) {
        const int buf = kt & 1;
        if (kt + 1 < n_tiles) {
            const int kb2 = (kt + 1) * 64;
            const unsigned* kp = g_k + ((size_t)(b * Sq + kb2)) * 64;
            const unsigned* vp = g_v + ((size_t)(b * Sq + kb2)) * 64;
            unsigned kd = ks_b + (unsigned)((buf ^ 1) * 4352) * 4u;
            unsigned vd = vs_b + (unsigned)((buf ^ 1) * 4608) * 4u;
#pragma unroll
            for (int i = 0; i < 4; i++) {
                int c = tid + i * 256;
                int r = c >> 4, col = (c & 15) * 4;
                CP16(kd + (unsigned)(r * 68 + col) * 4u, kp + r * 64 + col);
                CP16(vd + (unsigned)(r * 72 + col) * 4u, vp + r * 64 + col);
            }
            CPC;
            CPW(1);
        } else {
            CPW(0);
        }
        __syncthreads();

        const unsigned* Kc = Ks + buf * 4352;
        const unsigned* Vc = Vs + buf * 4608;
        const int kb = kt * 64;

        // S = Q K^T  (16 rows x 64 keys per warp)
        float sc[8][4];
#pragma unroll
        for (int nt = 0; nt < 8; nt++)
#pragma unroll
            for (int e = 0; e < 4; e++) sc[nt][e] = 0.f;
#pragma unroll
        for (int ks = 0; ks < 8; ks++) {
#pragma unroll
            for (int nt = 0; nt < 8; nt++) {
                unsigned b0 = Kc[(nt * 8 + g) * 68 + ks * 8 + tq];
                unsigned b1 = Kc[(nt * 8 + g) * 68 + ks * 8 + tq + 4];
                mma_tf32(sc[nt], qa[ks], b0, b1);
            }
        }

        // Causal mask (same qpos for both row-halves of this warp)
        if (kb + 63 > qpos) {
#pragma unroll
            for (int nt = 0; nt < 8; nt++) {
                int key = kb + nt * 8 + 2 * tq;
                if (key > qpos)     { sc[nt][0] = -1e30f; sc[nt][2] = -1e30f; }
                if (key + 1 > qpos) { sc[nt][1] = -1e30f; sc[nt][3] = -1e30f; }
            }
        }

        // Online softmax (rows = heads g and g+8; reduce over quad lanes)
        float mx0 = -1e30f, mx1 = -1e30f;
#pragma unroll
        for (int nt = 0; nt < 8; nt++) {
            mx0 = fmaxf(mx0, fmaxf(sc[nt][0], sc[nt][1]));
            mx1 = fmaxf(mx1, fmaxf(sc[nt][2], sc[nt][3]));
        }
        mx0 = fmaxf(mx0, __shfl_xor_sync(0xFFFFFFFFu, mx0, 1));
        mx0 = fmaxf(mx0, __shfl_xor_sync(0xFFFFFFFFu, mx0, 2));
        mx1 = fmaxf(mx1, __shfl_xor_sync(0xFFFFFFFFu, mx1, 1));
        mx1 = fmaxf(mx1, __shfl_xor_sync(0xFFFFFFFFu, mx1, 2));

        float mn0 = fmaxf(mr0, mx0);
        float mn1 = fmaxf(mr1, mx1);
        float corr0 = __expf(mr0 - mn0);
        float corr1 = __expf(mr1 - mn1);
        float sum0 = 0.f, sum1 = 0.f;
#pragma unroll
        for (int nt = 0; nt < 8; nt++) {
            sc[nt][0] = __expf(sc[nt][0] - mn0);
            sc[nt][1] = __expf(sc[nt][1] - mn0);
            sc[nt][2] = __expf(sc[nt][2] - mn1);
            sc[nt][3] = __expf(sc[nt][3] - mn1);
            sum0 += sc[nt][0] + sc[nt][1];
            sum1 += sc[nt][2] + sc[nt][3];
        }
        sum0 += __shfl_xor_sync(0xFFFFFFFFu, sum0, 1);
        sum0 += __shfl_xor_sync(0xFFFFFFFFu, sum0, 2);
        sum1 += __shfl_xor_sync(0xFFFFFFFFu, sum1, 1);
        sum1 += __shfl_xor_sync(0xFFFFFFFFu, sum1, 2);

        mr0 = mn0; mr1 = mn1;
        l0 = l0 * corr0 + sum0;
        l1 = l1 * corr1 + sum1;
#pragma unroll
        for (int nt = 0; nt < 8; nt++) {
            o[nt][0] *= corr0; o[nt][1] *= corr0;
            o[nt][2] *= corr1; o[nt][3] *= corr1;
        }

        // Store P (tf32) into this warp's private QP rows
#pragma unroll
        for (int nt = 0; nt < 8; nt++) {
            uint2 p0, p1;
            p0.x = f2tf32(sc[nt][0]); p0.y = f2tf32(sc[nt][1]);
            p1.x = f2tf32(sc[nt][2]); p1.y = f2tf32(sc[nt][3]);
            *(uint2*)&QP[r0 * 68 + nt * 8 + 2 * tq]       = p0;
            *(uint2*)&QP[(r0 + 8) * 68 + nt * 8 + 2 * tq] = p1;
        }
        __syncwarp();

        // O += P V
#pragma unroll
        for (int ks = 0; ks < 8; ks++) {
            unsigned pa[4];
            pa[0] = QP[r0 * 68 + ks * 8 + tq];
            pa[1] = QP[(r0 + 8) * 68 + ks * 8 + tq];
            pa[2] = QP[r0 * 68 + ks * 8 + tq + 4];
            pa[3] = QP[(r0 + 8) * 68 + ks * 8 + tq + 4];
#pragma unroll
            for (int nt = 0; nt < 8; nt++) {
                unsigned b0 = Vc[(ks * 8 + tq) * 72 + nt * 8 + g];
                unsigned b1 = Vc[(ks * 8 + tq + 4) * 72 + nt * 8 + g];
                mma_tf32(o[nt], pa, b0, b1);
            }
        }
        __syncthreads();
    }

    // Epilogue: normalize, write tf32 to g_attn[b][qpos][head*64+d]
    float inv0 = 1.f / l0;
    float inv1 = 1.f / l1;
    unsigned* dst0 = g_attn + (((size_t)(b * Sq + qpos)) << 10) + (g << 6);
    unsigned* dst1 = g_attn + (((size_t)(b * Sq + qpos)) << 10) + ((g + 8) << 6);
#pragma unroll
    for (int nt = 0; nt < 8; nt++) {
        int c = nt * 8 + 2 * tq;
        uint2 a0, a1;
        a0.x = f2tf32(o[nt][0] * inv0); a0.y = f2tf32(o[nt][1] * inv0);
        a1.x = f2tf32(o[nt][2] * inv1); a1.y = f2tf32(o[nt][3] * inv1);
        *(uint2*)&dst0[c] = a0;
        *(uint2*)&dst1[c] = a1;
    }
}

// ---------------------------------------------------------------------------
extern "C" void kernel_launch(void* const* d_in, const int* in_sizes, int n_in,
                              void* d_out, int out_size) {
    const float* x     = (const float*)d_in[0];
    const float* qkv_w = (const float*)d_in[1];
    const float* qkv_b = (const float*)d_in[2];
    const float* out_w = (const float*)d_in[3];
    const float* out_b = (const float*)d_in[4];
    float* out = (float*)d_out;

    const int GEMM_SMEM = 2 * 128 * 36 * 2 * 4;                    // 73728
    const int ATTN_SMEM = (128 * 68 + 2 * 64 * 68 + 2 * 64 * 72) * 4;  // 106496

    cudaFuncSetAttribute(gemm_qkv_kernel, cudaFuncAttributeMaxDynamicSharedMemorySize, GEMM_SMEM);
    cudaFuncSetAttribute(gemm_out_kernel, cudaFuncAttributeMaxDynamicSharedMemorySize, GEMM_SMEM);
    cudaFuncSetAttribute(attn_tc_kernel,  cudaFuncAttributeMaxDynamicSharedMemorySize, ATTN_SMEM);

    rope_tables_kernel<<<(Sq * 32 + 255) / 256, 256>>>();
    cvt_x_kernel<<<(Bq * Sq * Eq / 4 + 255) / 256, 256>>>(x);
    cvt_w1_kernel<<<(QKVq * Eq / 4 + 255) / 256, 256>>>(qkv_w);
    cvt_w2_kernel<<<(Eq * Eq / 4 + 255) / 256, 256>>>(out_w);

    gemm_qkv_kernel<<<dim3(QKVq / 128, (Bq * Sq) / 128), 256, GEMM_SMEM>>>(qkv_b);

    {
        int total = Bq * Sq * 18 * 32;
        rope_prep_kernel<<<(total + 255) / 256, 256>>>();
    }

    attn_tc_kernel<<<dim3(Sq / 8, Bq), 256, ATTN_SMEM>>>();

    gemm_out_kernel<<<dim3(Eq / 128, (Bq * Sq) / 128), 256, GEMM_SMEM>>>(out_b, out);
}

// round 4
// speedup vs baseline: 4.5628x; 1.0681x over previous
#include <cuda_runtime.h>
#include <math.h>

// Problem constants
#define Bq   2
#define Sq   2048
#define Eq   1024
#define Hq   16
#define QKVq 1152    // (16 + 2*1) * 64

// Scratch (device globals — no runtime allocation allowed)
__device__ unsigned g_q[(size_t)Bq * Sq * Eq];       // tf32, roped, scaled: [b*S+s][h*64+d]
__device__ unsigned g_k[(size_t)Bq * Sq * 64];       // tf32, roped
__device__ unsigned g_v[(size_t)Bq * Sq * 64];       // tf32
__device__ unsigned g_attn[(size_t)Bq * Sq * Eq];    // attention out (tf32)
__device__ float    g_cos[Sq * 32];
__device__ float    g_sin[Sq * 32];

// ---------------------------------------------------------------------------
__device__ __forceinline__ unsigned f2tf32(float x) {
    unsigned r;
    asm("cvt.rna.tf32.f32 %0, %1;" : "=r"(r) : "f"(x));
    return r;
}

__device__ __forceinline__ void mma_tf32(float* d, const unsigned* a,
                                         unsigned b0, unsigned b1) {
    asm volatile(
        "mma.sync.aligned.m16n8k8.row.col.f32.tf32.tf32.f32 "
        "{%0,%1,%2,%3}, {%4,%5,%6,%7}, {%8,%9}, {%0,%1,%2,%3};\n"
        : "+f"(d[0]), "+f"(d[1]), "+f"(d[2]), "+f"(d[3])
        : "r"(a[0]), "r"(a[1]), "r"(a[2]), "r"(a[3]), "r"(b0), "r"(b1));
}

#define CP16(dst, src) asm volatile("cp.async.cg.shared.global [%0], [%1], 16;\n" :: "r"(dst), "l"(src))
#define CPC            asm volatile("cp.async.commit_group;\n")
#define CPW(n)         asm volatile("cp.async.wait_group %0;\n" :: "n"(n))

// ---------------------------------------------------------------------------
// RoPE tables
// ---------------------------------------------------------------------------
__global__ void rope_tables_kernel() {
    int idx = blockIdx.x * blockDim.x + threadIdx.x;
    if (idx >= Sq * 32) return;
    int s = idx >> 5;
    int i = idx & 31;
    double inv = exp(-(2.0 * i / 64.0) * log(10000.0));
    double ang = (double)s * inv;
    g_cos[idx] = (float)cos(ang);
    g_sin[idx] = (float)sin(ang);
}

// ---------------------------------------------------------------------------
// Double-buffered tf32 tensor GEMM (NT): C = A * W^T + bias
// Block 128x128, BK=32, 256 thr (8 warps: 2m x 4n), warp tile 64x32.
// A/W staged as raw fp32 bits (tf32 mma reads high bits; truncation).
// ROPE=true: epilogue applies bias + RoPE + 0.125 scale and writes tf32
//            q/k/v directly (QKV projection). ROPE=false: bias + fp32 store.
// ---------------------------------------------------------------------------
template <int N, bool ROPE>
__device__ __forceinline__ void gemm_body(const unsigned* __restrict__ A,
                                          const unsigned* __restrict__ W,
                                          const float* __restrict__ bias,
                                          float* __restrict__ C) {
    extern __shared__ unsigned sm[];
    unsigned* sA = sm;                 // [2][128][36]
    unsigned* sB = sm + 2 * 128 * 36;  // [2][128][36]

    const int tid  = threadIdx.x;
    const int warp = tid >> 5;
    const int lane = tid & 31;
    const int g    = lane >> 2;
    const int tq   = lane & 3;
    const int wm   = (warp & 1) * 64;
    const int wn   = (warp >> 1) * 32;
    const int bm   = blockIdx.y * 128;
    const int bn   = blockIdx.x * 128;

    unsigned smb  = (unsigned)__cvta_generic_to_shared(sm);
    unsigned sA_b = smb;
    unsigned sB_b = smb + 2u * 128u * 36u * 4u;

    float acc[4][4][4];
#pragma unroll
    for (int mt = 0; mt < 4; mt++)
#pragma unroll
        for (int nt = 0; nt < 4; nt++)
#pragma unroll
            for (int e = 0; e < 4; e++) acc[mt][nt][e] = 0.f;

    // prologue stage buf 0
#pragma unroll
    for (int i = 0; i < 4; i++) {
        int c = tid + i * 256;
        int r = c >> 3, col = (c & 7) * 4;
        CP16(sA_b + (unsigned)(r * 36 + col) * 4u, A + (size_t)(bm + r) * Eq + col);
        CP16(sB_b + (unsigned)(r * 36 + col) * 4u, W + (size_t)(bn + r) * Eq + col);
    }
    CPC;

    for (int k0 = 0; k0 < Eq; k0 += 32) {
        int buf = (k0 >> 5) & 1;
        if (k0 + 32 < Eq) {
            unsigned da = sA_b + (unsigned)((buf ^ 1) * 4608) * 4u;
            unsigned db = sB_b + (unsigned)((buf ^ 1) * 4608) * 4u;
#pragma unroll
            for (int i = 0; i < 4; i++) {
                int c = tid + i * 256;
                int r = c >> 3, col = (c & 7) * 4;
                CP16(da + (unsigned)(r * 36 + col) * 4u, A + (size_t)(bm + r) * Eq + k0 + 32 + col);
                CP16(db + (unsigned)(r * 36 + col) * 4u, W + (size_t)(bn + r) * Eq + k0 + 32 + col);
            }
            CPC;
            CPW(1);
        } else {
            CPW(0);
        }
        __syncthreads();

        const unsigned* As_ = sA + buf * 4608;
        const unsigned* Bs_ = sB + buf * 4608;
#pragma unroll
        for (int ks = 0; ks < 4; ks++) {
            unsigned a[4][4];
#pragma unroll
            for (int mt = 0; mt < 4; mt++) {
                int r = wm + mt * 16 + g;
                a[mt][0] = As_[r * 36 + ks * 8 + tq];
                a[mt][1] = As_[(r + 8) * 36 + ks * 8 + tq];
                a[mt][2] = As_[r * 36 + ks * 8 + tq + 4];
                a[mt][3] = As_[(r + 8) * 36 + ks * 8 + tq + 4];
            }
#pragma unroll
            for (int nt = 0; nt < 4; nt++) {
                unsigned b0 = Bs_[(wn + nt * 8 + g) * 36 + ks * 8 + tq];
                unsigned b1 = Bs_[(wn + nt * 8 + g) * 36 + ks * 8 + tq + 4];
#pragma unroll
                for (int mt = 0; mt < 4; mt++)
                    mma_tf32(acc[mt][nt], a[mt], b0, b1);
            }
        }
        __syncthreads();
    }

    // Epilogue
#pragma unroll
    for (int mt = 0; mt < 4; mt++) {
        int m0 = bm + wm + mt * 16 + g;           // global row (b*Sq + s)
#pragma unroll
        for (int nt = 0; nt < 4; nt++) {
            int c = bn + wn + nt * 8 + 2 * tq;    // even column
            float bv0 = bias[c], bv1 = bias[c + 1];
            float v0 = acc[mt][nt][0] + bv0;      // row m0,   col c
            float v1 = acc[mt][nt][1] + bv1;      // row m0,   col c+1
            float v2 = acc[mt][nt][2] + bv0;      // row m0+8, col c
            float v3 = acc[mt][nt][3] + bv1;      // row m0+8, col c+1

            if (ROPE) {
                int s0 = m0 & (Sq - 1);
                int s8 = s0 + 8;                  // same batch (block rows aligned)
                if (c < 1024) {
                    // q head: rope pair (c, c+1), scale 0.125
                    int i = (c >> 1) & 31;
                    float c0 = g_cos[s0 * 32 + i], n0 = g_sin[s0 * 32 + i];
                    float c8 = g_cos[s8 * 32 + i], n8 = g_sin[s8 * 32 + i];
                    uint2 o0, o1;
                    o0.x = f2tf32((v0 * c0 - v1 * n0) * 0.125f);
                    o0.y = f2tf32((v0 * n0 + v1 * c0) * 0.125f);
                    o1.x = f2tf32((v2 * c8 - v3 * n8) * 0.125f);
                    o1.y = f2tf32((v2 * n8 + v3 * c8) * 0.125f);
                    *(uint2*)&g_q[(size_t)m0 * Eq + c]       = o0;
                    *(uint2*)&g_q[(size_t)(m0 + 8) * Eq + c] = o1;
                } else if (c < 1088) {
                    // k head: rope, no scale
                    int i = ((c - 1024) >> 1) & 31;
                    float c0 = g_cos[s0 * 32 + i], n0 = g_sin[s0 * 32 + i];
                    float c8 = g_cos[s8 * 32 + i], n8 = g_sin[s8 * 32 + i];
                    uint2 o0, o1;
                    o0.x = f2tf32(v0 * c0 - v1 * n0);
                    o0.y = f2tf32(v0 * n0 + v1 * c0);
                    o1.x = f2tf32(v2 * c8 - v3 * n8);
                    o1.y = f2tf32(v2 * n8 + v3 * c8);
                    *(uint2*)&g_k[(size_t)m0 * 64 + (c - 1024)]       = o0;
                    *(uint2*)&g_k[(size_t)(m0 + 8) * 64 + (c - 1024)] = o1;
                } else {
                    // v: plain copy
                    uint2 o0, o1;
                    o0.x = f2tf32(v0); o0.y = f2tf32(v1);
                    o1.x = f2tf32(v2); o1.y = f2tf32(v3);
                    *(uint2*)&g_v[(size_t)m0 * 64 + (c - 1088)]       = o0;
                    *(uint2*)&g_v[(size_t)(m0 + 8) * 64 + (c - 1088)] = o1;
                }
            } else {
                *(float2*)&C[(size_t)m0 * N + c]       = make_float2(v0, v1);
                *(float2*)&C[(size_t)(m0 + 8) * N + c] = make_float2(v2, v3);
            }
        }
    }
}

__global__ __launch_bounds__(256, 2) void gemm_qkv_kernel(const float* __restrict__ x,
                                                          const float* __restrict__ w,
                                                          const float* __restrict__ bias) {
    gemm_body<QKVq, true>((const unsigned*)x, (const unsigned*)w, bias, nullptr);
}

__global__ __launch_bounds__(256, 2) void gemm_out_kernel(const float* __restrict__ w,
                                                          const float* __restrict__ bias,
                                                          float* __restrict__ out) {
    gemm_body<Eq, false>(g_attn, (const unsigned*)w, bias, out);
}

// ---------------------------------------------------------------------------
// MQA flash attention, tensor-core, cp.async double-buffered.
// Block: 8 seq positions x all 16 heads = 128 mma rows; 256 thr, 8 warps.
// warp w = position qbase + w (16 head-rows). K/V staged ONCE for all heads.
// smem: QP 128x68 (Q then P), Ks 2x64x68, Vs 2x64x72  = 106496 B dynamic.
// ---------------------------------------------------------------------------
__global__ __launch_bounds__(256, 2) void attn_tc_kernel() {
    extern __shared__ unsigned sm[];
    unsigned* QP = sm;                               // 128*68
    unsigned* Ks = sm + 128 * 68;                    // 2*64*68
    unsigned* Vs = sm + 128 * 68 + 2 * 64 * 68;      // 2*64*72

    const int b     = blockIdx.y;
    const int qb    = 255 - (int)blockIdx.x;   // reversed: long blocks first
    const int qbase = qb * 8;
    const int tid   = threadIdx.x;
    const int w     = tid >> 5;
    const int lane  = tid & 31;
    const int g     = lane >> 2;
    const int tq    = lane & 3;

    unsigned smb  = (unsigned)__cvta_generic_to_shared(sm);
    const unsigned qp_b = smb;
    const unsigned ks_b = smb + 128u * 68u * 4u;
    const unsigned vs_b = smb + (128u * 68u + 2u * 64u * 68u) * 4u;

    // Stage Q: row r = pos_local*16 + head
#pragma unroll
    for (int i = 0; i < 8; i++) {
        int c = tid + i * 256;
        int r = c >> 4, col = (c & 15) * 4;
        const unsigned* src = g_q + (((size_t)(b * Sq + qbase + (r >> 4))) << 10)
                              + ((r & 15) << 6) + col;
        CP16(qp_b + (unsigned)(r * 68 + col) * 4u, src);
    }
    CPC;

    const int n_tiles = (qbase + 71) >> 6;

    // Stage KV tile 0
    {
        const unsigned* kp = g_k + ((size_t)(b * Sq)) * 64;
        const unsigned* vp = g_v + ((size_t)(b * Sq)) * 64;
#pragma unroll
        for (int i = 0; i < 4; i++) {
            int c = tid + i * 256;
            int r = c >> 4, col = (c & 15) * 4;
            CP16(ks_b + (unsigned)(r * 68 + col) * 4u, kp + r * 64 + col);
            CP16(vs_b + (unsigned)(r * 72 + col) * 4u, vp + r * 64 + col);
        }
    }
    CPC;
    CPW(1);            // Q done (KV0 may still be in flight)
    __syncthreads();

    // Preload Q fragments (warp's 16 rows), then QP is reused as P buffer
    const int r0 = w * 16 + g;
    unsigned qa[8][4];
#pragma unroll
    for (int ks = 0; ks < 8; ks++) {
        qa[ks][0] = QP[r0 * 68 + ks * 8 + tq];
        qa[ks][1] = QP[(r0 + 8) * 68 + ks * 8 + tq];
        qa[ks][2] = QP[r0 * 68 + ks * 8 + tq + 4];
        qa[ks][3] = QP[(r0 + 8) * 68 + ks * 8 + tq + 4];
    }

    float o[8][4];
#pragma unroll
    for (int nt = 0; nt < 8; nt++)
#pragma unroll
        for (int e = 0; e < 4; e++) o[nt][e] = 0.f;
    float mr0 = -1e30f, mr1 = -1e30f, l0 = 0.f, l1 = 0.f;
    const int qpos = qbase + w;

    for (int kt = 0; kt < n_tiles; kt++) {
        const int buf = kt & 1;
        if (kt + 1 < n_tiles) {
            const int kb2 = (kt + 1) * 64;
            const unsigned* kp = g_k + ((size_t)(b * Sq + kb2)) * 64;
            const unsigned* vp = g_v + ((size_t)(b * Sq + kb2)) * 64;
            unsigned kd = ks_b + (unsigned)((buf ^ 1) * 4352) * 4u;
            unsigned vd = vs_b + (unsigned)((buf ^ 1) * 4608) * 4u;
#pragma unroll
            for (int i = 0; i < 4; i++) {
                int c = tid + i * 256;
                int r = c >> 4, col = (c & 15) * 4;
                CP16(kd + (unsigned)(r * 68 + col) * 4u, kp + r * 64 + col);
                CP16(vd + (unsigned)(r * 72 + col) * 4u, vp + r * 64 + col);
            }
            CPC;
            CPW(1);
        } else {
            CPW(0);
        }
        __syncthreads();

        const unsigned* Kc = Ks + buf * 4352;
        const unsigned* Vc = Vs + buf * 4608;
        const int kb = kt * 64;

        // S = Q K^T  (16 rows x 64 keys per warp)
        float sc[8][4];
#pragma unroll
        for (int nt = 0; nt < 8; nt++)
#pragma unroll
            for (int e = 0; e < 4; e++) sc[nt][e] = 0.f;
#pragma unroll
        for (int ks = 0; ks < 8; ks++) {
#pragma unroll
            for (int nt = 0; nt < 8; nt++) {
                unsigned b0 = Kc[(nt * 8 + g) * 68 + ks * 8 + tq];
                unsigned b1 = Kc[(nt * 8 + g) * 68 + ks * 8 + tq + 4];
                mma_tf32(sc[nt], qa[ks], b0, b1);
            }
        }

        // Causal mask (same qpos for both row-halves of this warp)
        if (kb + 63 > qpos) {
#pragma unroll
            for (int nt = 0; nt < 8; nt++) {
                int key = kb + nt * 8 + 2 * tq;
                if (key > qpos)     { sc[nt][0] = -1e30f; sc[nt][2] = -1e30f; }
                if (key + 1 > qpos) { sc[nt][1] = -1e30f; sc[nt][3] = -1e30f; }
            }
        }

        // Online softmax (rows = heads g and g+8; reduce over quad lanes)
        float mx0 = -1e30f, mx1 = -1e30f;
#pragma unroll
        for (int nt = 0; nt < 8; nt++) {
            mx0 = fmaxf(mx0, fmaxf(sc[nt][0], sc[nt][1]));
            mx1 = fmaxf(mx1, fmaxf(sc[nt][2], sc[nt][3]));
        }
        mx0 = fmaxf(mx0, __shfl_xor_sync(0xFFFFFFFFu, mx0, 1));
        mx0 = fmaxf(mx0, __shfl_xor_sync(0xFFFFFFFFu, mx0, 2));
        mx1 = fmaxf(mx1, __shfl_xor_sync(0xFFFFFFFFu, mx1, 1));
        mx1 = fmaxf(mx1, __shfl_xor_sync(0xFFFFFFFFu, mx1, 2));

        float mn0 = fmaxf(mr0, mx0);
        float mn1 = fmaxf(mr1, mx1);
        float corr0 = __expf(mr0 - mn0);
        float corr1 = __expf(mr1 - mn1);
        float sum0 = 0.f, sum1 = 0.f;
#pragma unroll
        for (int nt = 0; nt < 8; nt++) {
            sc[nt][0] = __expf(sc[nt][0] - mn0);
            sc[nt][1] = __expf(sc[nt][1] - mn0);
            sc[nt][2] = __expf(sc[nt][2] - mn1);
            sc[nt][3] = __expf(sc[nt][3] - mn1);
            sum0 += sc[nt][0] + sc[nt][1];
            sum1 += sc[nt][2] + sc[nt][3];
        }
        sum0 += __shfl_xor_sync(0xFFFFFFFFu, sum0, 1);
        sum0 += __shfl_xor_sync(0xFFFFFFFFu, sum0, 2);
        sum1 += __shfl_xor_sync(0xFFFFFFFFu, sum1, 1);
        sum1 += __shfl_xor_sync(0xFFFFFFFFu, sum1, 2);

        mr0 = mn0; mr1 = mn1;
        l0 = l0 * corr0 + sum0;
        l1 = l1 * corr1 + sum1;
#pragma unroll
        for (int nt = 0; nt < 8; nt++) {
            o[nt][0] *= corr0; o[nt][1] *= corr0;
            o[nt][2] *= corr1; o[nt][3] *= corr1;
        }

        // Store P (tf32) into this warp's private QP rows
#pragma unroll
        for (int nt = 0; nt < 8; nt++) {
            uint2 p0, p1;
            p0.x = f2tf32(sc[nt][0]); p0.y = f2tf32(sc[nt][1]);
            p1.x = f2tf32(sc[nt][2]); p1.y = f2tf32(sc[nt][3]);
            *(uint2*)&QP[r0 * 68 + nt * 8 + 2 * tq]       = p0;
            *(uint2*)&QP[(r0 + 8) * 68 + nt * 8 + 2 * tq] = p1;
        }
        __syncwarp();

        // O += P V
#pragma unroll
        for (int ks = 0; ks < 8; ks++) {
            unsigned pa[4];
            pa[0] = QP[r0 * 68 + ks * 8 + tq];
            pa[1] = QP[(r0 + 8) * 68 + ks * 8 + tq];
            pa[2] = QP[r0 * 68 + ks * 8 + tq + 4];
            pa[3] = QP[(r0 + 8) * 68 + ks * 8 + tq + 4];
#pragma unroll
            for (int nt = 0; nt < 8; nt++) {
                unsigned b0 = Vc[(ks * 8 + tq) * 72 + nt * 8 + g];
                unsigned b1 = Vc[(ks * 8 + tq + 4) * 72 + nt * 8 + g];
                mma_tf32(o[nt], pa, b0, b1);
            }
        }
        __syncthreads();
    }

    // Epilogue: normalize, write tf32 to g_attn[b][qpos][head*64+d]
    float inv0 = 1.f / l0;
    float inv1 = 1.f / l1;
    unsigned* dst0 = g_attn + (((size_t)(b * Sq + qpos)) << 10) + (g << 6);
    unsigned* dst1 = g_attn + (((size_t)(b * Sq + qpos)) << 10) + ((g + 8) << 6);
#pragma unroll
    for (int nt = 0; nt < 8; nt++) {
        int c = nt * 8 + 2 * tq;
        uint2 a0, a1;
        a0.x = f2tf32(o[nt][0] * inv0); a0.y = f2tf32(o[nt][1] * inv0);
        a1.x = f2tf32(o[nt][2] * inv1); a1.y = f2tf32(o[nt][3] * inv1);
        *(uint2*)&dst0[c] = a0;
        *(uint2*)&dst1[c] = a1;
    }
}

// ---------------------------------------------------------------------------
extern "C" void kernel_launch(void* const* d_in, const int* in_sizes, int n_in,
                              void* d_out, int out_size) {
    const float* x     = (const float*)d_in[0];
    const float* qkv_w = (const float*)d_in[1];
    const float* qkv_b = (const float*)d_in[2];
    const float* out_w = (const float*)d_in[3];
    const float* out_b = (const float*)d_in[4];
    float* out = (float*)d_out;

    const int GEMM_SMEM = 2 * 128 * 36 * 2 * 4;                        // 73728
    const int ATTN_SMEM = (128 * 68 + 2 * 64 * 68 + 2 * 64 * 72) * 4;  // 106496

    cudaFuncSetAttribute(gemm_qkv_kernel, cudaFuncAttributeMaxDynamicSharedMemorySize, GEMM_SMEM);
    cudaFuncSetAttribute(gemm_out_kernel, cudaFuncAttributeMaxDynamicSharedMemorySize, GEMM_SMEM);
    cudaFuncSetAttribute(attn_tc_kernel,  cudaFuncAttributeMaxDynamicSharedMemorySize, ATTN_SMEM);

    // 1. RoPE tables (must precede QKV GEMM epilogue)
    rope_tables_kernel<<<(Sq * 32 + 255) / 256, 256>>>();

    // 2. QKV projection + bias + RoPE + scale + tf32 pack (fused epilogue)
    gemm_qkv_kernel<<<dim3(QKVq / 128, (Bq * Sq) / 128), 256, GEMM_SMEM>>>(x, qkv_w, qkv_b);

    // 3. Causal MQA flash attention -> g_attn (tf32)
    attn_tc_kernel<<<dim3(Sq / 8, Bq), 256, ATTN_SMEM>>>();

    // 4. Output projection + bias -> out (fp32)
    gemm_out_kernel<<<dim3(Eq / 128, (Bq * Sq) / 128), 256, GEMM_SMEM>>>(out_w, out_b, out);
}